// round 14
// baseline (speedup 1.0000x reference)
#include <cuda_runtime.h>
#include <cuda_fp16.h>
#include <stdint.h>
#include <math.h>

#define NMAX 100000

__device__ __align__(16) float g_segsum[(size_t)NMAX * 64];
__device__ float g_cnt[NMAX];
__device__ float g_esum[64];
__device__ float g_nsum[64];

// fp16 hi-only weight fragments uint2 = {b0,b1}, layout [kc][nt8][lane]
__device__ __align__(16) uint2 g_w1f[13 * 16 * 32];
__device__ __align__(16) uint2 g_w2f[8 * 8 * 32];
__device__ __align__(16) uint2 g_wn1f[9 * 16 * 32];
__device__ __align__(16) uint2 g_wn2f[8 * 8 * 32];

// ---------------- helpers ----------------
__device__ __forceinline__ uint32_t smem_u32(const void* p) {
    uint32_t a;
    asm("{ .reg .u64 t; cvta.to.shared.u64 t, %1; cvt.u32.u64 %0, t; }" : "=r"(a) : "l"(p));
    return a;
}
#define LDSM_X4(r, a) asm volatile( \
    "ldmatrix.sync.aligned.m8n8.x4.shared.b16 {%0,%1,%2,%3}, [%4];" \
    : "=r"((r)[0]), "=r"((r)[1]), "=r"((r)[2]), "=r"((r)[3]) : "r"(a))
#define MMA16816(d, a, b0, b1) asm volatile( \
    "mma.sync.aligned.m16n8k16.row.col.f32.f16.f16.f32 " \
    "{%0,%1,%2,%3}, {%4,%5,%6,%7}, {%8,%9}, {%0,%1,%2,%3};" \
    : "+f"((d)[0]), "+f"((d)[1]), "+f"((d)[2]), "+f"((d)[3]) \
    : "r"((a)[0]), "r"((a)[1]), "r"((a)[2]), "r"((a)[3]), "r"(b0), "r"(b1))
#define BARC256(id) asm volatile("bar.sync %0, 256;" :: "r"(id) : "memory")

__device__ __forceinline__ void mbar_init(uint32_t m, uint32_t c) {
    asm volatile("mbarrier.init.shared.b64 [%0], %1;" :: "r"(m), "r"(c) : "memory");
}
__device__ __forceinline__ void mbar_arrive(uint32_t m) {
    asm volatile("mbarrier.arrive.shared.b64 _, [%0];" :: "r"(m) : "memory");
}
__device__ __forceinline__ void mbar_wait(uint32_t m, int ph) {
    asm volatile("{ .reg .pred P;\nLW%=: mbarrier.try_wait.parity.acquire.cta.shared::cta.b64 P, [%0], %1, 0x989680;\n@P bra LD%=;\nbra LW%=;\nLD%=: }"
                 :: "r"(m), "r"(ph) : "memory");
}
__device__ __forceinline__ void redv2(float* p, float a, float b) {
    asm volatile("{ .reg .u64 q; cvta.to.global.u64 q, %0;\n"
                 "red.global.add.v2.f32 [q], {%1,%2}; }"
                 :: "l"(p), "f"(a), "f"(b) : "memory");
}

// ---------------- setup ----------------
__global__ void zero_kernel(int N) {
    size_t i = (size_t)blockIdx.x * blockDim.x + threadIdx.x;
    if (i < (size_t)N * 16) ((float4*)g_segsum)[i] = make_float4(0.f, 0.f, 0.f, 0.f);
    if (i < (size_t)N) g_cnt[i] = 0.f;
    if (i < 64) { g_esum[i] = 0.f; g_nsum[i] = 0.f; }
}
__device__ __forceinline__ uint2 mkfrag2(const float* W, int ncols, int kc, int nt8, int lane) {
    int k0 = kc * 16 + 2 * (lane & 3);
    int n  = nt8 * 8 + (lane >> 2);
    __half2 a = __floats2half2_rn(W[(size_t)k0 * ncols + n], W[(size_t)(k0 + 1) * ncols + n]);
    __half2 b = __floats2half2_rn(W[(size_t)(k0 + 8) * ncols + n], W[(size_t)(k0 + 9) * ncols + n]);
    return make_uint2(*(uint32_t*)&a, *(uint32_t*)&b);
}
__global__ void prep_weights(const float* We1, const float* We2,
                             const float* Wn1, const float* Wn2) {
    int i = blockIdx.x * blockDim.x + threadIdx.x;
    if (i < 13 * 16 * 32) { int kc = i >> 9, r = i & 511; g_w1f[i] = mkfrag2(We1, 128, kc, r >> 5, r & 31); return; }
    i -= 13 * 16 * 32;
    if (i < 8 * 8 * 32)   { int kc = i >> 8, r = i & 255; g_w2f[i] = mkfrag2(We2, 64, kc, r >> 5, r & 31); return; }
    i -= 8 * 8 * 32;
    if (i < 9 * 16 * 32)  { int kc = i >> 9, r = i & 511; g_wn1f[i] = mkfrag2(Wn1, 128, kc, r >> 5, r & 31); return; }
    i -= 9 * 16 * 32;
    if (i < 8 * 8 * 32)   { int kc = i >> 8, r = i & 255; g_wn2f[i] = mkfrag2(Wn2, 64, kc, r >> 5, r & 31); }
}

// ---------------- consumer MLP: 8 warps (2M x 4N), 128-row tile ----------------
// Each warp: 64 rows (4 m-tiles of 16), GEMM1 cols [32wn,+32), GEMM2 cols [16wn,+16).
// A fp16 (byte stride SA2), H fp16 (stride 272B).
template<int SA2, int KC1>
__device__ __forceinline__ void tile_mlp(char* sm, uint32_t sbase,
    uint32_t offA, uint32_t offH,
    const uint2* __restrict__ W1f, const uint2* __restrict__ W2f,
    const float* b1s, int wm, int wn, int lane, uint32_t emptyAddr,
    float (&d2)[4][2][4])
{
    float d1[4][4][4];
#pragma unroll
    for (int m = 0; m < 4; m++)
#pragma unroll
        for (int j = 0; j < 4; j++)
#pragma unroll
            for (int k = 0; k < 4; k++) d1[m][j][k] = 0.f;

    const uint32_t aA = sbase + offA +
        (uint32_t)(64 * wm * SA2 + (lane & 15) * SA2 + (lane >> 4) * 16);
    const uint2* __restrict__ w1p = W1f + 4 * wn * 32 + lane;

    for (int kc = 0; kc < KC1; kc++) {
        uint32_t ah[4][4];
#pragma unroll
        for (int m = 0; m < 4; m++)
            LDSM_X4(ah[m], aA + (uint32_t)(m * 16 * SA2) + kc * 32);
        uint2 w[4];
#pragma unroll
        for (int j = 0; j < 4; j++) w[j] = __ldg(w1p + kc * 512 + j * 32);
#pragma unroll
        for (int m = 0; m < 4; m++)
#pragma unroll
            for (int j = 0; j < 4; j++)
                MMA16816(d1[m][j], ah[m], w[j].x, w[j].y);
    }
    mbar_arrive(emptyAddr);   // A slot free for producer

    // epi1: H = relu(D1 + b1) -> fp16, stride 136 halves (272B)
#pragma unroll
    for (int m = 0; m < 4; m++)
#pragma unroll
        for (int j = 0; j < 4; j++) {
            int c = 32 * wn + 8 * j + 2 * (lane & 3);
            int R = 64 * wm + 16 * m + (lane >> 2);
            __half2 p0 = __floats2half2_rn(fmaxf(d1[m][j][0] + b1s[c], 0.f),
                                           fmaxf(d1[m][j][1] + b1s[c + 1], 0.f));
            *(__half2*)(sm + offH + (R * 136 + c) * 2) = p0;
            __half2 p1 = __floats2half2_rn(fmaxf(d1[m][j][2] + b1s[c], 0.f),
                                           fmaxf(d1[m][j][3] + b1s[c + 1], 0.f));
            *(__half2*)(sm + offH + ((R + 8) * 136 + c) * 2) = p1;
        }
    BARC256(1);   // H visible to all consumer warps

    // GEMM2: 64 rows x 16 cols per warp, K=128, single term (Hh * W2h)
#pragma unroll
    for (int m = 0; m < 4; m++)
#pragma unroll
        for (int j = 0; j < 2; j++)
#pragma unroll
            for (int k = 0; k < 4; k++) d2[m][j][k] = 0.f;

    const uint32_t aH = sbase + offH +
        (uint32_t)(64 * wm * 272 + (lane & 15) * 272 + (lane >> 4) * 16);
    const uint2* __restrict__ w2p = W2f + 2 * wn * 32 + lane;

#pragma unroll
    for (int kc = 0; kc < 8; kc++) {
        uint32_t hh[4][4];
#pragma unroll
        for (int m = 0; m < 4; m++)
            LDSM_X4(hh[m], aH + (uint32_t)(m * 16 * 272) + kc * 32);
        uint2 w0 = __ldg(w2p + kc * 256);
        uint2 w1 = __ldg(w2p + kc * 256 + 32);
#pragma unroll
        for (int m = 0; m < 4; m++) {
            MMA16816(d2[m][0], hh[m], w0.x, w0.y);
            MMA16816(d2[m][1], hh[m], w1.x, w1.y);
        }
    }
    BARC256(1);   // all H reads done -> next tile's epi1 may overwrite H
}

// ---------------- edge kernel ----------------
extern __shared__ char dsm[];

#define E_SA2  432
#define E_SLOT 55296u
#define E_H    110592u
#define E_SMEM 145408

__global__ __launch_bounds__(384, 1)
void edge_tc(const float* __restrict__ x, const int* __restrict__ ei,
             const float* __restrict__ ea, const float* __restrict__ gf,
             const float* __restrict__ b1, const float* __restrict__ b2,
             float* __restrict__ eout, int E, int N, int ntiles)
{
    __shared__ float b1s[128], b2s[64], redbuf[64];
    __shared__ __align__(16) unsigned long long s_bar[4];
    const int tid = threadIdx.x, lane = tid & 31;
    const uint32_t sbase = smem_u32(dsm);
    const uint32_t bfull = smem_u32(&s_bar[0]), bempty = smem_u32(&s_bar[2]);

    if (tid < 128) b1s[tid] = b1[tid];
    if (tid < 64)  { b2s[tid] = b2[tid]; redbuf[tid] = 0.f; }
    if (tid == 0) {
        mbar_init(bfull, 128); mbar_init(bfull + 8, 128);
        mbar_init(bempty, 256); mbar_init(bempty + 8, 256);
    }
    __syncthreads();

    if (tid < 256) {  // ---- consumers (8 warps: 2M x 4N) ----
        const int wid = tid >> 5, wm = wid >> 2, wn = wid & 3;
        float acc[2][2] = {{0.f, 0.f}, {0.f, 0.f}};
        int i = 0;
        for (int t = blockIdx.x; t < ntiles; t += gridDim.x, i++) {
            int s = i & 1, ph = (i >> 1) & 1;
            mbar_wait(bfull + 8 * s, ph);
            float d2[4][2][4];
            tile_mlp<E_SA2, 13>(dsm, sbase, s * E_SLOT, E_H,
                                g_w1f, g_w2f, b1s, wm, wn, lane, bempty + 8 * s, d2);
#pragma unroll
            for (int m = 0; m < 4; m++)
#pragma unroll
                for (int h = 0; h < 2; h++) {
                    int row = 64 * wm + 16 * m + (lane >> 2) + 8 * h;
                    int ge = t * 128 + row;
                    if (ge < E) {
                        int r = ei[ge]; r = min(max(r, 0), N - 1);  // re-load (slot-safe)
#pragma unroll
                        for (int j = 0; j < 2; j++) {
                            int c = 16 * wn + 8 * j + 2 * (lane & 3);
                            float v0 = d2[m][j][2 * h]     + b2s[c];
                            float v1 = d2[m][j][2 * h + 1] + b2s[c + 1];
                            *(float2*)(eout + (size_t)ge * 64 + c) = make_float2(v0, v1);
                            redv2(g_segsum + (size_t)r * 64 + c, v0, v1);
                            acc[j][0] += v0; acc[j][1] += v1;
                        }
                        if (wn == 0 && (lane & 3) == 0) atomicAdd(&g_cnt[r], 1.f);
                    }
                }
        }
#pragma unroll
        for (int j = 0; j < 2; j++) {
            atomicAdd(&redbuf[16 * wn + 8 * j + 2 * (lane & 3)], acc[j][0]);
            atomicAdd(&redbuf[16 * wn + 8 * j + 2 * (lane & 3) + 1], acc[j][1]);
        }
        BARC256(2);
        if (tid < 64) atomicAdd(&g_esum[tid], redbuf[tid]);
    } else {  // ---- producers (4 warps, 1 thread per row) ----
        const int e = tid - 256;   // 0..127
        int i = 0;
        for (int t = blockIdx.x; t < ntiles; t += gridDim.x, i++) {
            int s = i & 1;
            if (i >= 2) mbar_wait(bempty + 8 * s, ((i >> 1) + 1) & 1);
            int ge = t * 128 + e;
            bool v = ge < E;
            int r = 0, c = 0;
            if (v) {
                r = ei[ge]; c = ei[E + ge];
                r = min(max(r, 0), N - 1); c = min(max(c, 0), N - 1);
            }
            char* sb = dsm + s * E_SLOT;
            const float4* g4 = (const float4*)gf;
            const float4* xr = (const float4*)(x + (size_t)r * 64);
            const float4* xc = (const float4*)(x + (size_t)c * 64);
            const float4* e4 = (const float4*)(ea + (size_t)ge * 64);
#pragma unroll
            for (int b = 0; b < 4; b++) {
                float4 vv[13];
#pragma unroll
                for (int j = 0; j < 13; j++) {
                    int c4 = b * 13 + j;
                    float4 w = make_float4(0.f, 0.f, 0.f, 0.f);
                    if (v) {
                        if (c4 < 4) w = g4[c4];
                        else if (c4 < 20) w = xr[c4 - 4];
                        else if (c4 < 36) w = xc[c4 - 20];
                        else w = e4[c4 - 36];
                    }
                    vv[j] = w;
                }
#pragma unroll
                for (int j = 0; j < 13; j++) {
                    int c4 = b * 13 + j;
                    __half2 h0 = __floats2half2_rn(vv[j].x, vv[j].y);
                    __half2 h1 = __floats2half2_rn(vv[j].z, vv[j].w);
                    *(uint2*)(sb + (uint32_t)(e * E_SA2 + c4 * 8)) =
                        make_uint2(*(uint32_t*)&h0, *(uint32_t*)&h1);
                }
            }
            mbar_arrive(bfull + 8 * s);
        }
    }
}

// ---------------- node kernel ----------------
#define N_SA2  304
#define N_SLOT 38912u
#define N_H    77824u
#define N_SMEM 112640

__global__ __launch_bounds__(384, 1)
void node_tc(const float* __restrict__ x, const float* __restrict__ gf,
             const float* __restrict__ b1, const float* __restrict__ b2,
             float* __restrict__ nout, int N, int ntiles)
{
    __shared__ float b1s[128], b2s[64], redbuf[64];
    __shared__ __align__(16) unsigned long long s_bar[4];
    const int tid = threadIdx.x, lane = tid & 31;
    const uint32_t sbase = smem_u32(dsm);
    const uint32_t bfull = smem_u32(&s_bar[0]), bempty = smem_u32(&s_bar[2]);

    if (tid < 128) b1s[tid] = b1[tid];
    if (tid < 64)  { b2s[tid] = b2[tid]; redbuf[tid] = 0.f; }
    if (tid == 0) {
        mbar_init(bfull, 128); mbar_init(bfull + 8, 128);
        mbar_init(bempty, 256); mbar_init(bempty + 8, 256);
    }
    __syncthreads();

    if (tid < 256) {  // consumers
        const int wid = tid >> 5, wm = wid >> 2, wn = wid & 3;
        float acc[2][2] = {{0.f, 0.f}, {0.f, 0.f}};
        int i = 0;
        for (int t = blockIdx.x; t < ntiles; t += gridDim.x, i++) {
            int s = i & 1, ph = (i >> 1) & 1;
            mbar_wait(bfull + 8 * s, ph);
            float d2[4][2][4];
            tile_mlp<N_SA2, 9>(dsm, sbase, s * N_SLOT, N_H,
                               g_wn1f, g_wn2f, b1s, wm, wn, lane, bempty + 8 * s, d2);
#pragma unroll
            for (int m = 0; m < 4; m++)
#pragma unroll
                for (int h = 0; h < 2; h++) {
                    int row = 64 * wm + 16 * m + (lane >> 2) + 8 * h;
                    int n = t * 128 + row;
                    if (n < N) {
#pragma unroll
                        for (int j = 0; j < 2; j++) {
                            int c = 16 * wn + 8 * j + 2 * (lane & 3);
                            float v0 = d2[m][j][2 * h]     + b2s[c];
                            float v1 = d2[m][j][2 * h + 1] + b2s[c + 1];
                            *(float2*)(nout + (size_t)n * 64 + c) = make_float2(v0, v1);
                            acc[j][0] += v0; acc[j][1] += v1;
                        }
                    }
                }
        }
#pragma unroll
        for (int j = 0; j < 2; j++) {
            atomicAdd(&redbuf[16 * wn + 8 * j + 2 * (lane & 3)], acc[j][0]);
            atomicAdd(&redbuf[16 * wn + 8 * j + 2 * (lane & 3) + 1], acc[j][1]);
        }
        BARC256(2);
        if (tid < 64) atomicAdd(&g_nsum[tid], redbuf[tid]);
    } else {  // producers (4 warps, 1 thread per row)
        const int e = tid - 256;
        int i = 0;
        for (int t = blockIdx.x; t < ntiles; t += gridDim.x, i++) {
            int s = i & 1;
            if (i >= 2) mbar_wait(bempty + 8 * s, ((i >> 1) + 1) & 1);
            int n = t * 128 + e;
            bool v = n < N;
            float inv = 1.f;
            if (v) inv = 1.0f / fmaxf(g_cnt[n], 1.0f);
            char* sb = dsm + s * N_SLOT;
            const float4* g4 = (const float4*)gf;
            const float4* xn = (const float4*)(x + (size_t)n * 64);
            const float4* sg = (const float4*)(g_segsum + (size_t)n * 64);
#pragma unroll
            for (int b = 0; b < 4; b++) {
                float4 vv[9];
#pragma unroll
                for (int j = 0; j < 9; j++) {
                    int c4 = b * 9 + j;
                    float4 w = make_float4(0.f, 0.f, 0.f, 0.f);
                    if (v) {
                        if (c4 < 4) w = g4[c4];
                        else if (c4 < 20) w = xn[c4 - 4];
                        else {
                            float4 p = sg[c4 - 20];
                            w = make_float4(p.x * inv, p.y * inv, p.z * inv, p.w * inv);
                        }
                    }
                    vv[j] = w;
                }
#pragma unroll
                for (int j = 0; j < 9; j++) {
                    int c4 = b * 9 + j;
                    __half2 h0 = __floats2half2_rn(vv[j].x, vv[j].y);
                    __half2 h1 = __floats2half2_rn(vv[j].z, vv[j].w);
                    *(uint2*)(sb + (uint32_t)(e * N_SA2 + c4 * 8)) =
                        make_uint2(*(uint32_t*)&h0, *(uint32_t*)&h1);
                }
            }
            mbar_arrive(bfull + 8 * s);
        }
    }
}

// ---------------- global kernel ----------------
__global__ void global_kernel(const float* __restrict__ g,
                              const float* __restrict__ Wg1, const float* __restrict__ bg1,
                              const float* __restrict__ Wg2, const float* __restrict__ bg2,
                              float* __restrict__ out, int N, int E)
{
    __shared__ float in[144], h[128];
    int t = threadIdx.x;
    if (t < 64)       in[t] = g_nsum[t] / (float)N;
    else if (t < 128) in[t] = g_esum[t - 64] / (float)E;
    else if (t < 144) in[t] = g[t - 128];
    __syncthreads();
    if (t < 128) {
        float s = bg1[t];
        for (int k = 0; k < 144; k++) s += in[k] * Wg1[(size_t)k * 128 + t];
        h[t] = fmaxf(s, 0.f);
    }
    __syncthreads();
    if (t < 16) {
        float s = bg2[t];
        for (int k = 0; k < 128; k++) s += h[k] * Wg2[(size_t)k * 16 + t];
        out[t] = s;
    }
}

// ---------------- launch ----------------
extern "C" void kernel_launch(void* const* d_in, const int* in_sizes, int n_in,
                              void* d_out, int out_size)
{
    const float* x   = (const float*)d_in[0];
    const int*   ei  = (const int*)d_in[1];
    const float* ea  = (const float*)d_in[2];
    const float* g   = (const float*)d_in[3];
    const float* We1 = (const float*)d_in[4];
    const float* be1 = (const float*)d_in[5];
    const float* We2 = (const float*)d_in[6];
    const float* be2 = (const float*)d_in[7];
    const float* Wn1 = (const float*)d_in[8];
    const float* bn1 = (const float*)d_in[9];
    const float* Wn2 = (const float*)d_in[10];
    const float* bn2 = (const float*)d_in[11];
    const float* Wg1 = (const float*)d_in[12];
    const float* bg1 = (const float*)d_in[13];
    const float* Wg2 = (const float*)d_in[14];
    const float* bg2 = (const float*)d_in[15];

    int N = in_sizes[0] / 64;
    int E = in_sizes[1] / 2;
    float* eout = (float*)d_out;
    float* nout = eout + (size_t)E * 64;
    float* gout = nout + (size_t)N * 64;

    cudaFuncSetAttribute(edge_tc, cudaFuncAttributeMaxDynamicSharedMemorySize, E_SMEM);
    cudaFuncSetAttribute(node_tc, cudaFuncAttributeMaxDynamicSharedMemorySize, N_SMEM);

    zero_kernel<<<(N * 16 + 255) / 256, 256>>>(N);
    prep_weights<<<60, 256>>>(We1, We2, Wn1, Wn2);

    int etiles = (E + 127) / 128;
    int ntl    = (N + 127) / 128;
    edge_tc<<<148, 384, E_SMEM>>>(x, ei, ea, g, be1, be2, eout, E, N, etiles);
    node_tc<<<148, 384, N_SMEM>>>(x, g, bn1, bn2, nout, N, ntl);
    global_kernel<<<1, 160>>>(g, Wg1, bg1, Wg2, bg2, gout, N, E);
}

// round 15
// speedup vs baseline: 1.0478x; 1.0478x over previous
#include <cuda_runtime.h>
#include <cuda_fp16.h>
#include <stdint.h>
#include <math.h>

#define NMAX 100000

__device__ __align__(16) float g_segsum[(size_t)NMAX * 64];
__device__ float g_cnt[NMAX];
__device__ float g_esum[64];
__device__ float g_nsum[64];

// fp16 hi-only weight fragments uint2 = {b0,b1}, layout [kc][nt8][lane]
__device__ __align__(16) uint2 g_w1f[13 * 16 * 32];
__device__ __align__(16) uint2 g_w2f[8 * 8 * 32];
__device__ __align__(16) uint2 g_wn1f[9 * 16 * 32];
__device__ __align__(16) uint2 g_wn2f[8 * 8 * 32];

// ---------------- helpers ----------------
__device__ __forceinline__ uint32_t smem_u32(const void* p) {
    uint32_t a;
    asm("{ .reg .u64 t; cvta.to.shared.u64 t, %1; cvt.u32.u64 %0, t; }" : "=r"(a) : "l"(p));
    return a;
}
#define LDSM_X4(r, a) asm volatile( \
    "ldmatrix.sync.aligned.m8n8.x4.shared.b16 {%0,%1,%2,%3}, [%4];" \
    : "=r"((r)[0]), "=r"((r)[1]), "=r"((r)[2]), "=r"((r)[3]) : "r"(a))
#define MMA16816(d, a, b0, b1) asm volatile( \
    "mma.sync.aligned.m16n8k16.row.col.f32.f16.f16.f32 " \
    "{%0,%1,%2,%3}, {%4,%5,%6,%7}, {%8,%9}, {%0,%1,%2,%3};" \
    : "+f"((d)[0]), "+f"((d)[1]), "+f"((d)[2]), "+f"((d)[3]) \
    : "r"((a)[0]), "r"((a)[1]), "r"((a)[2]), "r"((a)[3]), "r"(b0), "r"(b1))
#define BARC256(id) asm volatile("bar.sync %0, 256;" :: "r"(id) : "memory")

__device__ __forceinline__ void mbar_init(uint32_t m, uint32_t c) {
    asm volatile("mbarrier.init.shared.b64 [%0], %1;" :: "r"(m), "r"(c) : "memory");
}
__device__ __forceinline__ void mbar_arrive(uint32_t m) {
    asm volatile("mbarrier.arrive.shared.b64 _, [%0];" :: "r"(m) : "memory");
}
__device__ __forceinline__ void mbar_wait(uint32_t m, int ph) {
    asm volatile("{ .reg .pred P;\nLW%=: mbarrier.try_wait.parity.acquire.cta.shared::cta.b64 P, [%0], %1, 0x989680;\n@P bra LD%=;\nbra LW%=;\nLD%=: }"
                 :: "r"(m), "r"(ph) : "memory");
}
__device__ __forceinline__ void redv2(float* p, float a, float b) {
    asm volatile("{ .reg .u64 q; cvta.to.global.u64 q, %0;\n"
                 "red.global.add.v2.f32 [q], {%1,%2}; }"
                 :: "l"(p), "f"(a), "f"(b) : "memory");
}
__device__ __forceinline__ void redv4(float* p, float a, float b, float c, float d) {
    asm volatile("{ .reg .u64 q; cvta.to.global.u64 q, %0;\n"
                 "red.global.add.v4.f32 [q], {%1,%2,%3,%4}; }"
                 :: "l"(p), "f"(a), "f"(b), "f"(c), "f"(d) : "memory");
}

// ---------------- setup ----------------
__global__ void zero_kernel(int N) {
    size_t i = (size_t)blockIdx.x * blockDim.x + threadIdx.x;
    if (i < (size_t)N * 16) ((float4*)g_segsum)[i] = make_float4(0.f, 0.f, 0.f, 0.f);
    if (i < (size_t)N) g_cnt[i] = 0.f;
    if (i < 64) { g_esum[i] = 0.f; g_nsum[i] = 0.f; }
}
__device__ __forceinline__ uint2 mkfrag2(const float* W, int ncols, int kc, int nt8, int lane) {
    int k0 = kc * 16 + 2 * (lane & 3);
    int n  = nt8 * 8 + (lane >> 2);
    __half2 a = __floats2half2_rn(W[(size_t)k0 * ncols + n], W[(size_t)(k0 + 1) * ncols + n]);
    __half2 b = __floats2half2_rn(W[(size_t)(k0 + 8) * ncols + n], W[(size_t)(k0 + 9) * ncols + n]);
    return make_uint2(*(uint32_t*)&a, *(uint32_t*)&b);
}
__global__ void prep_weights(const float* We1, const float* We2,
                             const float* Wn1, const float* Wn2) {
    int i = blockIdx.x * blockDim.x + threadIdx.x;
    if (i < 13 * 16 * 32) { int kc = i >> 9, r = i & 511; g_w1f[i] = mkfrag2(We1, 128, kc, r >> 5, r & 31); return; }
    i -= 13 * 16 * 32;
    if (i < 8 * 8 * 32)   { int kc = i >> 8, r = i & 255; g_w2f[i] = mkfrag2(We2, 64, kc, r >> 5, r & 31); return; }
    i -= 8 * 8 * 32;
    if (i < 9 * 16 * 32)  { int kc = i >> 9, r = i & 511; g_wn1f[i] = mkfrag2(Wn1, 128, kc, r >> 5, r & 31); return; }
    i -= 9 * 16 * 32;
    if (i < 8 * 8 * 32)   { int kc = i >> 8, r = i & 255; g_wn2f[i] = mkfrag2(Wn2, 64, kc, r >> 5, r & 31); }
}

// ---------------- consumer MLP: 8 warps (2M x 4N), 64-row tile ----------------
template<int SA2, int KC1>
__device__ __forceinline__ void tile_mlp(char* sm, uint32_t sbase,
    uint32_t offA, uint32_t offH,
    const uint2* __restrict__ W1f, const uint2* __restrict__ W2f,
    const float* b1s, int wm, int wn, int lane, uint32_t emptyAddr,
    float (&d2)[2][2][4])
{
    float d1[2][4][4];
#pragma unroll
    for (int m = 0; m < 2; m++)
#pragma unroll
        for (int j = 0; j < 4; j++)
#pragma unroll
            for (int k = 0; k < 4; k++) d1[m][j][k] = 0.f;

    const uint32_t aA = sbase + offA +
        (uint32_t)(32 * wm * SA2 + (lane & 15) * SA2 + (lane >> 4) * 16);
    const uint2* __restrict__ w1p = W1f + 4 * wn * 32 + lane;

    for (int kc = 0; kc < KC1; kc++) {
        uint32_t ah[2][4];
        LDSM_X4(ah[0], aA + kc * 32);
        LDSM_X4(ah[1], aA + (uint32_t)(16 * SA2) + kc * 32);
        uint2 w[4];
#pragma unroll
        for (int j = 0; j < 4; j++) w[j] = __ldg(w1p + kc * 512 + j * 32);
#pragma unroll
        for (int m = 0; m < 2; m++)
#pragma unroll
            for (int j = 0; j < 4; j++)
                MMA16816(d1[m][j], ah[m], w[j].x, w[j].y);
    }
    mbar_arrive(emptyAddr);   // A slot free for producer

    // epi1: H = relu(D1 + b1) -> fp16, stride 136 halves (272B)
#pragma unroll
    for (int m = 0; m < 2; m++)
#pragma unroll
        for (int j = 0; j < 4; j++) {
            int c = 32 * wn + 8 * j + 2 * (lane & 3);
            int R = 32 * wm + 16 * m + (lane >> 2);
            __half2 p0 = __floats2half2_rn(fmaxf(d1[m][j][0] + b1s[c], 0.f),
                                           fmaxf(d1[m][j][1] + b1s[c + 1], 0.f));
            *(__half2*)(sm + offH + (R * 136 + c) * 2) = p0;
            __half2 p1 = __floats2half2_rn(fmaxf(d1[m][j][2] + b1s[c], 0.f),
                                           fmaxf(d1[m][j][3] + b1s[c + 1], 0.f));
            *(__half2*)(sm + offH + ((R + 8) * 136 + c) * 2) = p1;
        }
    BARC256(1);   // H visible to all consumer warps

    // GEMM2: 32 rows x 16 cols per warp, K=128, single term (Hh * W2h)
#pragma unroll
    for (int m = 0; m < 2; m++)
#pragma unroll
        for (int j = 0; j < 2; j++)
#pragma unroll
            for (int k = 0; k < 4; k++) d2[m][j][k] = 0.f;

    const uint32_t aH = sbase + offH +
        (uint32_t)(32 * wm * 272 + (lane & 15) * 272 + (lane >> 4) * 16);
    const uint2* __restrict__ w2p = W2f + 2 * wn * 32 + lane;

#pragma unroll
    for (int kc = 0; kc < 8; kc++) {
        uint32_t hh[2][4];
        LDSM_X4(hh[0], aH + kc * 32);
        LDSM_X4(hh[1], aH + (uint32_t)(16 * 272) + kc * 32);
        uint2 w0 = __ldg(w2p + kc * 256);
        uint2 w1 = __ldg(w2p + kc * 256 + 32);
#pragma unroll
        for (int m = 0; m < 2; m++) {
            MMA16816(d2[m][0], hh[m], w0.x, w0.y);
            MMA16816(d2[m][1], hh[m], w1.x, w1.y);
        }
    }
    BARC256(1);   // all H reads done -> next tile's epi1 may overwrite H
}

// ---------------- edge kernel ----------------
extern __shared__ char dsm[];

#define E_SA2  432
#define E_SLOT 27648u
#define E_H    55296u
#define E_D2   72704u
#define E_D2SZ 17408u
#define E_SMEM 107520

__global__ __launch_bounds__(512, 1)
void edge_tc(const float* __restrict__ x, const int* __restrict__ ei,
             const float* __restrict__ ea, const float* __restrict__ gf,
             const float* __restrict__ b1, const float* __restrict__ b2,
             float* __restrict__ eout, int E, int N, int ntiles)
{
    __shared__ float b1s[128], b2s[64], redbuf[64];
    __shared__ __align__(16) unsigned long long s_bar[8];
    const int tid = threadIdx.x, lane = tid & 31;
    const uint32_t sbase = smem_u32(dsm);
    const uint32_t bAf = smem_u32(&s_bar[0]), bAe = smem_u32(&s_bar[2]);
    const uint32_t bDf = smem_u32(&s_bar[4]), bDe = smem_u32(&s_bar[6]);

    if (tid < 128) b1s[tid] = b1[tid];
    if (tid < 64)  { b2s[tid] = b2[tid]; redbuf[tid] = 0.f; }
    if (tid == 0) {
        mbar_init(bAf, 256); mbar_init(bAf + 8, 256);
        mbar_init(bAe, 256); mbar_init(bAe + 8, 256);
        mbar_init(bDf, 256); mbar_init(bDf + 8, 256);
        mbar_init(bDe, 256); mbar_init(bDe + 8, 256);
    }
    __syncthreads();

    if (tid < 256) {  // ---- consumers: GEMMs + D2 staging only ----
        const int wid = tid >> 5, wm = wid >> 2, wn = wid & 3;
        float acc[2][2] = {{0.f, 0.f}, {0.f, 0.f}};
        int i = 0;
        for (int t = blockIdx.x; t < ntiles; t += gridDim.x, i++) {
            int s = i & 1, ph = (i >> 1) & 1;
            mbar_wait(bAf + 8 * s, ph);
            float d2[2][2][4];
            tile_mlp<E_SA2, 13>(dsm, sbase, s * E_SLOT, E_H,
                                g_w1f, g_w2f, b1s, wm, wn, lane, bAe + 8 * s, d2);
            if (i >= 2) mbar_wait(bDe + 8 * s, ((i >> 1) + 1) & 1);
            float* sD2 = (float*)(dsm + E_D2 + s * E_D2SZ);
#pragma unroll
            for (int m = 0; m < 2; m++)
#pragma unroll
                for (int h = 0; h < 2; h++) {
                    int row = 32 * wm + 16 * m + (lane >> 2) + 8 * h;
                    bool v = (t * 64 + row) < E;
#pragma unroll
                    for (int j = 0; j < 2; j++) {
                        int c = 16 * wn + 8 * j + 2 * (lane & 3);
                        float v0 = d2[m][j][2 * h]     + b2s[c];
                        float v1 = d2[m][j][2 * h + 1] + b2s[c + 1];
                        *(float2*)&sD2[row * 68 + c] = make_float2(v0, v1);
                        if (v) { acc[j][0] += v0; acc[j][1] += v1; }
                    }
                }
            mbar_arrive(bDf + 8 * s);
        }
#pragma unroll
        for (int j = 0; j < 2; j++) {
            atomicAdd(&redbuf[16 * wn + 8 * j + 2 * (lane & 3)], acc[j][0]);
            atomicAdd(&redbuf[16 * wn + 8 * j + 2 * (lane & 3) + 1], acc[j][1]);
        }
        BARC256(2);
        if (tid < 64) atomicAdd(&g_esum[tid], redbuf[tid]);
    } else {  // ---- producers: gather + scatter ----
        const int pt = tid - 256;
        const int e = pt >> 2, q = pt & 3;
        int i = 0, prev_t = -1, k = 0;
        for (int t = blockIdx.x; t < ntiles; t += gridDim.x, i++) {
            int s = i & 1;
            if (i >= 2) mbar_wait(bAe + 8 * s, ((i >> 1) + 1) & 1);
            int ge = t * 64 + e;
            bool v = ge < E;
            int r = 0, c = 0;
            if (v) {
                r = ei[ge]; c = ei[E + ge];
                r = min(max(r, 0), N - 1); c = min(max(c, 0), N - 1);
            }
            char* sb = dsm + s * E_SLOT;
            const float4* g4 = (const float4*)gf;
            const float4* xr = (const float4*)(x + (size_t)r * 64);
            const float4* xc = (const float4*)(x + (size_t)c * 64);
            const float4* e4 = (const float4*)(ea + (size_t)ge * 64);
            float4 vv[13];
#pragma unroll
            for (int j = 0; j < 13; j++) {
                int c4 = q + 4 * j;
                float4 w = make_float4(0.f, 0.f, 0.f, 0.f);
                if (v) {
                    if (c4 < 4) w = g4[c4];
                    else if (c4 < 20) w = xr[c4 - 4];
                    else if (c4 < 36) w = xc[c4 - 20];
                    else w = e4[c4 - 36];
                }
                vv[j] = w;
            }
#pragma unroll
            for (int j = 0; j < 13; j++) {
                int c4 = q + 4 * j;
                __half2 h0 = __floats2half2_rn(vv[j].x, vv[j].y);
                __half2 h1 = __floats2half2_rn(vv[j].z, vv[j].w);
                *(uint2*)(sb + (uint32_t)(e * E_SA2 + c4 * 8)) =
                    make_uint2(*(uint32_t*)&h0, *(uint32_t*)&h1);
            }
            mbar_arrive(bAf + 8 * s);

            // scatter the previous tile's D2
            if (prev_t >= 0) {
                int sp = k & 1;
                mbar_wait(bDf + 8 * sp, (k >> 1) & 1);
                int gep = prev_t * 64 + e;
                if (gep < E) {
                    int rp = ei[gep]; rp = min(max(rp, 0), N - 1);
                    const float* sD2 = (const float*)(dsm + E_D2 + sp * E_D2SZ);
#pragma unroll
                    for (int kk = 0; kk < 4; kk++) {
                        int cc = q * 16 + 4 * kk;
                        float4 w = *(const float4*)&sD2[e * 68 + cc];
                        *(float4*)(eout + (size_t)gep * 64 + cc) = w;
                        redv4(g_segsum + (size_t)rp * 64 + cc, w.x, w.y, w.z, w.w);
                    }
                    if (q == 0) atomicAdd(&g_cnt[rp], 1.f);
                }
                mbar_arrive(bDe + 8 * sp);
                k++;
            }
            prev_t = t;
        }
        if (prev_t >= 0) {   // tail scatter
            int sp = k & 1;
            mbar_wait(bDf + 8 * sp, (k >> 1) & 1);
            int gep = prev_t * 64 + e;
            if (gep < E) {
                int rp = ei[gep]; rp = min(max(rp, 0), N - 1);
                const float* sD2 = (const float*)(dsm + E_D2 + sp * E_D2SZ);
#pragma unroll
                for (int kk = 0; kk < 4; kk++) {
                    int cc = q * 16 + 4 * kk;
                    float4 w = *(const float4*)&sD2[e * 68 + cc];
                    *(float4*)(eout + (size_t)gep * 64 + cc) = w;
                    redv4(g_segsum + (size_t)rp * 64 + cc, w.x, w.y, w.z, w.w);
                }
                if (q == 0) atomicAdd(&g_cnt[rp], 1.f);
            }
            mbar_arrive(bDe + 8 * sp);
        }
    }
}

// ---------------- node kernel (Round-12 layout, unchanged) ----------------
#define N_SA2  304
#define N_SLOT 19456u
#define N_H    38912u
#define N_SMEM 56320

__global__ __launch_bounds__(512, 1)
void node_tc(const float* __restrict__ x, const float* __restrict__ gf,
             const float* __restrict__ b1, const float* __restrict__ b2,
             float* __restrict__ nout, int N, int ntiles)
{
    __shared__ float b1s[128], b2s[64], redbuf[64];
    __shared__ __align__(16) unsigned long long s_bar[4];
    const int tid = threadIdx.x, lane = tid & 31;
    const uint32_t sbase = smem_u32(dsm);
    const uint32_t bfull = smem_u32(&s_bar[0]), bempty = smem_u32(&s_bar[2]);

    if (tid < 128) b1s[tid] = b1[tid];
    if (tid < 64)  { b2s[tid] = b2[tid]; redbuf[tid] = 0.f; }
    if (tid == 0) {
        mbar_init(bfull, 256); mbar_init(bfull + 8, 256);
        mbar_init(bempty, 256); mbar_init(bempty + 8, 256);
    }
    __syncthreads();

    if (tid < 256) {  // consumers
        const int wid = tid >> 5, wm = wid >> 2, wn = wid & 3;
        float acc[2][2] = {{0.f, 0.f}, {0.f, 0.f}};
        int i = 0;
        for (int t = blockIdx.x; t < ntiles; t += gridDim.x, i++) {
            int s = i & 1, ph = (i >> 1) & 1;
            mbar_wait(bfull + 8 * s, ph);
            float d2[2][2][4];
            tile_mlp<N_SA2, 9>(dsm, sbase, s * N_SLOT, N_H,
                               g_wn1f, g_wn2f, b1s, wm, wn, lane, bempty + 8 * s, d2);
#pragma unroll
            for (int m = 0; m < 2; m++)
#pragma unroll
                for (int h = 0; h < 2; h++) {
                    int row = 32 * wm + 16 * m + (lane >> 2) + 8 * h;
                    int n = t * 64 + row;
                    if (n < N) {
#pragma unroll
                        for (int j = 0; j < 2; j++) {
                            int c = 16 * wn + 8 * j + 2 * (lane & 3);
                            float v0 = d2[m][j][2 * h]     + b2s[c];
                            float v1 = d2[m][j][2 * h + 1] + b2s[c + 1];
                            *(float2*)(nout + (size_t)n * 64 + c) = make_float2(v0, v1);
                            acc[j][0] += v0; acc[j][1] += v1;
                        }
                    }
                }
        }
#pragma unroll
        for (int j = 0; j < 2; j++) {
            atomicAdd(&redbuf[16 * wn + 8 * j + 2 * (lane & 3)], acc[j][0]);
            atomicAdd(&redbuf[16 * wn + 8 * j + 2 * (lane & 3) + 1], acc[j][1]);
        }
        BARC256(2);
        if (tid < 64) atomicAdd(&g_nsum[tid], redbuf[tid]);
    } else {  // producers
        const int pt = tid - 256;
        const int e = pt >> 2, q = pt & 3;
        int i = 0;
        for (int t = blockIdx.x; t < ntiles; t += gridDim.x, i++) {
            int s = i & 1;
            if (i >= 2) mbar_wait(bempty + 8 * s, ((i >> 1) + 1) & 1);
            int n = t * 64 + e;
            bool v = n < N;
            float inv = 1.f;
            if (v) inv = 1.0f / fmaxf(g_cnt[n], 1.0f);
            char* sb = dsm + s * N_SLOT;
            const float4* g4 = (const float4*)gf;
            const float4* xn = (const float4*)(x + (size_t)n * 64);
            const float4* sg = (const float4*)(g_segsum + (size_t)n * 64);
            float4 vv[9];
#pragma unroll
            for (int j = 0; j < 9; j++) {
                int c4 = q + 4 * j;
                float4 w = make_float4(0.f, 0.f, 0.f, 0.f);
                if (v) {
                    if (c4 < 4) w = g4[c4];
                    else if (c4 < 20) w = xn[c4 - 4];
                    else {
                        float4 p = sg[c4 - 20];
                        w = make_float4(p.x * inv, p.y * inv, p.z * inv, p.w * inv);
                    }
                }
                vv[j] = w;
            }
#pragma unroll
            for (int j = 0; j < 9; j++) {
                int c4 = q + 4 * j;
                __half2 h0 = __floats2half2_rn(vv[j].x, vv[j].y);
                __half2 h1 = __floats2half2_rn(vv[j].z, vv[j].w);
                *(uint2*)(sb + (uint32_t)(e * N_SA2 + c4 * 8)) =
                    make_uint2(*(uint32_t*)&h0, *(uint32_t*)&h1);
            }
            mbar_arrive(bfull + 8 * s);
        }
    }
}

// ---------------- global kernel ----------------
__global__ void global_kernel(const float* __restrict__ g,
                              const float* __restrict__ Wg1, const float* __restrict__ bg1,
                              const float* __restrict__ Wg2, const float* __restrict__ bg2,
                              float* __restrict__ out, int N, int E)
{
    __shared__ float in[144], h[128];
    int t = threadIdx.x;
    if (t < 64)       in[t] = g_nsum[t] / (float)N;
    else if (t < 128) in[t] = g_esum[t - 64] / (float)E;
    else if (t < 144) in[t] = g[t - 128];
    __syncthreads();
    if (t < 128) {
        float s = bg1[t];
        for (int k = 0; k < 144; k++) s += in[k] * Wg1[(size_t)k * 128 + t];
        h[t] = fmaxf(s, 0.f);
    }
    __syncthreads();
    if (t < 16) {
        float s = bg2[t];
        for (int k = 0; k < 128; k++) s += h[k] * Wg2[(size_t)k * 16 + t];
        out[t] = s;
    }
}

// ---------------- launch ----------------
extern "C" void kernel_launch(void* const* d_in, const int* in_sizes, int n_in,
                              void* d_out, int out_size)
{
    const float* x   = (const float*)d_in[0];
    const int*   ei  = (const int*)d_in[1];
    const float* ea  = (const float*)d_in[2];
    const float* g   = (const float*)d_in[3];
    const float* We1 = (const float*)d_in[4];
    const float* be1 = (const float*)d_in[5];
    const float* We2 = (const float*)d_in[6];
    const float* be2 = (const float*)d_in[7];
    const float* Wn1 = (const float*)d_in[8];
    const float* bn1 = (const float*)d_in[9];
    const float* Wn2 = (const float*)d_in[10];
    const float* bn2 = (const float*)d_in[11];
    const float* Wg1 = (const float*)d_in[12];
    const float* bg1 = (const float*)d_in[13];
    const float* Wg2 = (const float*)d_in[14];
    const float* bg2 = (const float*)d_in[15];

    int N = in_sizes[0] / 64;
    int E = in_sizes[1] / 2;
    float* eout = (float*)d_out;
    float* nout = eout + (size_t)E * 64;
    float* gout = nout + (size_t)N * 64;

    cudaFuncSetAttribute(edge_tc, cudaFuncAttributeMaxDynamicSharedMemorySize, E_SMEM);
    cudaFuncSetAttribute(node_tc, cudaFuncAttributeMaxDynamicSharedMemorySize, N_SMEM);

    zero_kernel<<<(N * 16 + 255) / 256, 256>>>(N);
    prep_weights<<<60, 256>>>(We1, We2, Wn1, Wn2);

    int etiles = (E + 63) / 64;
    int ntl    = (N + 63) / 64;
    edge_tc<<<148, 512, E_SMEM>>>(x, ei, ea, g, be1, be2, eout, E, N, etiles);
    node_tc<<<148, 512, N_SMEM>>>(x, g, bn1, bn2, nout, N, ntl);
    global_kernel<<<1, 160>>>(g, Wg1, bg1, Wg2, bg2, gout, N, E);
}

// round 16
// speedup vs baseline: 1.1731x; 1.1195x over previous
#include <cuda_runtime.h>
#include <cuda_fp16.h>
#include <stdint.h>
#include <math.h>

#define NMAX 100000

__device__ __align__(16) float g_segsum[(size_t)NMAX * 64];
__device__ float g_cnt[NMAX];
__device__ float g_esum[64];
__device__ float g_nsum[64];

// fp16 hi-only weight fragments uint2 = {b0,b1}, layout [kc][nt8][lane]
__device__ __align__(16) uint2 g_w1f[13 * 16 * 32];
__device__ __align__(16) uint2 g_w2f[8 * 8 * 32];
__device__ __align__(16) uint2 g_wn1f[9 * 16 * 32];
__device__ __align__(16) uint2 g_wn2f[8 * 8 * 32];

// ---------------- helpers ----------------
__device__ __forceinline__ uint32_t smem_u32(const void* p) {
    uint32_t a;
    asm("{ .reg .u64 t; cvta.to.shared.u64 t, %1; cvt.u32.u64 %0, t; }" : "=r"(a) : "l"(p));
    return a;
}
#define LDSM_X4(r, a) asm volatile( \
    "ldmatrix.sync.aligned.m8n8.x4.shared.b16 {%0,%1,%2,%3}, [%4];" \
    : "=r"((r)[0]), "=r"((r)[1]), "=r"((r)[2]), "=r"((r)[3]) : "r"(a))
#define MMA16816(d, a, b0, b1) asm volatile( \
    "mma.sync.aligned.m16n8k16.row.col.f32.f16.f16.f32 " \
    "{%0,%1,%2,%3}, {%4,%5,%6,%7}, {%8,%9}, {%0,%1,%2,%3};" \
    : "+f"((d)[0]), "+f"((d)[1]), "+f"((d)[2]), "+f"((d)[3]) \
    : "r"((a)[0]), "r"((a)[1]), "r"((a)[2]), "r"((a)[3]), "r"(b0), "r"(b1))
#define BARC256(id) asm volatile("bar.sync %0, 256;" :: "r"(id) : "memory")

__device__ __forceinline__ void mbar_init(uint32_t m, uint32_t c) {
    asm volatile("mbarrier.init.shared.b64 [%0], %1;" :: "r"(m), "r"(c) : "memory");
}
__device__ __forceinline__ void mbar_arrive(uint32_t m) {
    asm volatile("mbarrier.arrive.shared.b64 _, [%0];" :: "r"(m) : "memory");
}
__device__ __forceinline__ void mbar_wait(uint32_t m, int ph) {
    asm volatile("{ .reg .pred P;\nLW%=: mbarrier.try_wait.parity.acquire.cta.shared::cta.b64 P, [%0], %1, 0x989680;\n@P bra LD%=;\nbra LW%=;\nLD%=: }"
                 :: "r"(m), "r"(ph) : "memory");
}
__device__ __forceinline__ void redv2(float* p, float a, float b) {
    asm volatile("{ .reg .u64 q; cvta.to.global.u64 q, %0;\n"
                 "red.global.add.v2.f32 [q], {%1,%2}; }"
                 :: "l"(p), "f"(a), "f"(b) : "memory");
}

// ---------------- fused setup: zero scratch + build weight fragments ----------------
__device__ __forceinline__ uint2 mkfrag2(const float* W, int ncols, int kc, int nt8, int lane) {
    int k0 = kc * 16 + 2 * (lane & 3);
    int n  = nt8 * 8 + (lane >> 2);
    __half2 a = __floats2half2_rn(W[(size_t)k0 * ncols + n], W[(size_t)(k0 + 1) * ncols + n]);
    __half2 b = __floats2half2_rn(W[(size_t)(k0 + 8) * ncols + n], W[(size_t)(k0 + 9) * ncols + n]);
    return make_uint2(*(uint32_t*)&a, *(uint32_t*)&b);
}
__global__ void setup_kernel(int N, const float* We1, const float* We2,
                             const float* Wn1, const float* Wn2) {
    size_t gi = (size_t)blockIdx.x * blockDim.x + threadIdx.x;
    if (gi < (size_t)N * 16) ((float4*)g_segsum)[gi] = make_float4(0.f, 0.f, 0.f, 0.f);
    if (gi < (size_t)N) g_cnt[gi] = 0.f;
    if (gi < 64) { g_esum[gi] = 0.f; g_nsum[gi] = 0.f; }
    int i = (int)gi;
    if (i < 13 * 16 * 32) { int kc = i >> 9, r = i & 511; g_w1f[i] = mkfrag2(We1, 128, kc, r >> 5, r & 31); return; }
    i -= 13 * 16 * 32;
    if (i < 8 * 8 * 32)   { int kc = i >> 8, r = i & 255; g_w2f[i] = mkfrag2(We2, 64, kc, r >> 5, r & 31); return; }
    i -= 8 * 8 * 32;
    if (i < 9 * 16 * 32)  { int kc = i >> 9, r = i & 511; g_wn1f[i] = mkfrag2(Wn1, 128, kc, r >> 5, r & 31); return; }
    i -= 9 * 16 * 32;
    if (i < 8 * 8 * 32)   { int kc = i >> 8, r = i & 255; g_wn2f[i] = mkfrag2(Wn2, 64, kc, r >> 5, r & 31); }
}

// ---------------- consumer MLP: 8 warps (2M x 4N), 64-row tile ----------------
// A fp16 (byte stride SA2), H fp16 (stride 272B), double-buffered H -> one barrier.
template<int SA2, int KC1>
__device__ __forceinline__ void tile_mlp(char* sm, uint32_t sbase,
    uint32_t offA, uint32_t offH,
    const uint2* __restrict__ W1f, const uint2* __restrict__ W2f,
    const float* b1s, int wm, int wn, int lane, uint32_t emptyAddr,
    float (&d2)[2][2][4])
{
    float d1[2][4][4];
#pragma unroll
    for (int m = 0; m < 2; m++)
#pragma unroll
        for (int j = 0; j < 4; j++)
#pragma unroll
            for (int k = 0; k < 4; k++) d1[m][j][k] = 0.f;

    const uint32_t aA = sbase + offA +
        (uint32_t)(32 * wm * SA2 + (lane & 15) * SA2 + (lane >> 4) * 16);
    const uint2* __restrict__ w1p = W1f + 4 * wn * 32 + lane;

    for (int kc = 0; kc < KC1; kc++) {
        uint32_t ah[2][4];
        LDSM_X4(ah[0], aA + kc * 32);
        LDSM_X4(ah[1], aA + (uint32_t)(16 * SA2) + kc * 32);
        uint2 w[4];
#pragma unroll
        for (int j = 0; j < 4; j++) w[j] = __ldg(w1p + kc * 512 + j * 32);
#pragma unroll
        for (int m = 0; m < 2; m++)
#pragma unroll
            for (int j = 0; j < 4; j++)
                MMA16816(d1[m][j], ah[m], w[j].x, w[j].y);
    }
    mbar_arrive(emptyAddr);   // A slot free for producer

    // epi1: H = relu(D1 + b1) -> fp16, stride 136 halves (272B)
#pragma unroll
    for (int m = 0; m < 2; m++)
#pragma unroll
        for (int j = 0; j < 4; j++) {
            int c = 32 * wn + 8 * j + 2 * (lane & 3);
            int R = 32 * wm + 16 * m + (lane >> 2);
            __half2 p0 = __floats2half2_rn(fmaxf(d1[m][j][0] + b1s[c], 0.f),
                                           fmaxf(d1[m][j][1] + b1s[c + 1], 0.f));
            *(__half2*)(sm + offH + (R * 136 + c) * 2) = p0;
            __half2 p1 = __floats2half2_rn(fmaxf(d1[m][j][2] + b1s[c], 0.f),
                                           fmaxf(d1[m][j][3] + b1s[c + 1], 0.f));
            *(__half2*)(sm + offH + ((R + 8) * 136 + c) * 2) = p1;
        }
    BARC256(1);   // H visible to all consumer warps (only barrier per tile)

    // GEMM2: 32 rows x 16 cols per warp, K=128, single term (Hh * W2h)
#pragma unroll
    for (int m = 0; m < 2; m++)
#pragma unroll
        for (int j = 0; j < 2; j++)
#pragma unroll
            for (int k = 0; k < 4; k++) d2[m][j][k] = 0.f;

    const uint32_t aH = sbase + offH +
        (uint32_t)(32 * wm * 272 + (lane & 15) * 272 + (lane >> 4) * 16);
    const uint2* __restrict__ w2p = W2f + 2 * wn * 32 + lane;

#pragma unroll
    for (int kc = 0; kc < 8; kc++) {
        uint32_t hh[2][4];
        LDSM_X4(hh[0], aH + kc * 32);
        LDSM_X4(hh[1], aH + (uint32_t)(16 * 272) + kc * 32);
        uint2 w0 = __ldg(w2p + kc * 256);
        uint2 w1 = __ldg(w2p + kc * 256 + 32);
#pragma unroll
        for (int m = 0; m < 2; m++) {
            MMA16816(d2[m][0], hh[m], w0.x, w0.y);
            MMA16816(d2[m][1], hh[m], w1.x, w1.y);
        }
    }
    // no trailing barrier: H double-buffered; tile i+2's epi1 (same H slot)
    // is ordered after this GEMM2 by the BARC at tile i+1.
}

// ---------------- edge kernel ----------------
extern __shared__ char dsm[];

#define E_SA2  432
#define E_SLOT 27648u
#define E_HB   82944u
#define E_HSZ  17408u
#define E_SMEM 117760

__global__ __launch_bounds__(512, 1)
void edge_tc(const float* __restrict__ x, const int* __restrict__ ei,
             const float* __restrict__ ea, const float* __restrict__ gf,
             const float* __restrict__ b1, const float* __restrict__ b2,
             float* __restrict__ eout, int E, int N, int ntiles)
{
    __shared__ float b1s[128], b2s[64], redbuf[64];
    __shared__ __align__(16) unsigned long long s_bar[6];  // full0..2, empty0..2
    const int tid = threadIdx.x, lane = tid & 31;
    const uint32_t sbase = smem_u32(dsm);
    const uint32_t bAf = smem_u32(&s_bar[0]), bAe = smem_u32(&s_bar[3]);

    if (tid < 128) b1s[tid] = b1[tid];
    if (tid < 64)  { b2s[tid] = b2[tid]; redbuf[tid] = 0.f; }
    if (tid == 0) {
#pragma unroll
        for (int s = 0; s < 3; s++) {
            mbar_init(bAf + 8 * s, 256);
            mbar_init(bAe + 8 * s, 256);
        }
    }
    __syncthreads();

    if (tid < 256) {  // ---- consumers (8 warps: 2M x 4N) ----
        const int wid = tid >> 5, wm = wid >> 2, wn = wid & 3;
        float acc[2][2] = {{0.f, 0.f}, {0.f, 0.f}};
        int s = 0, wrap = 0, it = 0;
        for (int t = blockIdx.x; t < ntiles; t += gridDim.x) {
            mbar_wait(bAf + 8 * s, wrap & 1);
            float d2[2][2][4];
            tile_mlp<E_SA2, 13>(dsm, sbase, s * E_SLOT, E_HB + (uint32_t)(it & 1) * E_HSZ,
                                g_w1f, g_w2f, b1s, wm, wn, lane, bAe + 8 * s, d2);
#pragma unroll
            for (int m = 0; m < 2; m++)
#pragma unroll
                for (int h = 0; h < 2; h++) {
                    int row = 32 * wm + 16 * m + (lane >> 2) + 8 * h;
                    int ge = t * 64 + row;
                    if (ge < E) {
                        int r = ei[ge]; r = min(max(r, 0), N - 1);
#pragma unroll
                        for (int j = 0; j < 2; j++) {
                            int c = 16 * wn + 8 * j + 2 * (lane & 3);
                            float v0 = d2[m][j][2 * h]     + b2s[c];
                            float v1 = d2[m][j][2 * h + 1] + b2s[c + 1];
                            *(float2*)(eout + (size_t)ge * 64 + c) = make_float2(v0, v1);
                            redv2(g_segsum + (size_t)r * 64 + c, v0, v1);
                            acc[j][0] += v0; acc[j][1] += v1;
                        }
                        if (wn == 0 && (lane & 3) == 0) atomicAdd(&g_cnt[r], 1.f);
                    }
                }
            s++; if (s == 3) { s = 0; wrap++; }
            it++;
        }
#pragma unroll
        for (int j = 0; j < 2; j++) {
            atomicAdd(&redbuf[16 * wn + 8 * j + 2 * (lane & 3)], acc[j][0]);
            atomicAdd(&redbuf[16 * wn + 8 * j + 2 * (lane & 3) + 1], acc[j][1]);
        }
        BARC256(2);
        if (tid < 64) atomicAdd(&g_esum[tid], redbuf[tid]);
    } else {  // ---- producers (8 warps, 4 threads/row) ----
        const int pt = tid - 256;
        const int e = pt >> 2, q = pt & 3;
        int s = 0, wrap = 0, it = 0;
        for (int t = blockIdx.x; t < ntiles; t += gridDim.x) {
            if (it >= 3) mbar_wait(bAe + 8 * s, (wrap - 1) & 1);
            int ge = t * 64 + e;
            bool v = ge < E;
            int r = 0, c = 0;
            if (v) {
                r = ei[ge]; c = ei[E + ge];
                r = min(max(r, 0), N - 1); c = min(max(c, 0), N - 1);
            }
            char* sb = dsm + s * E_SLOT;
            const float4* g4 = (const float4*)gf;
            const float4* xr = (const float4*)(x + (size_t)r * 64);
            const float4* xc = (const float4*)(x + (size_t)c * 64);
            const float4* e4 = (const float4*)(ea + (size_t)ge * 64);
            float4 vv[13];
#pragma unroll
            for (int j = 0; j < 13; j++) {
                int c4 = q + 4 * j;
                float4 w = make_float4(0.f, 0.f, 0.f, 0.f);
                if (v) {
                    if (c4 < 4) w = g4[c4];
                    else if (c4 < 20) w = xr[c4 - 4];
                    else if (c4 < 36) w = xc[c4 - 20];
                    else w = e4[c4 - 36];
                }
                vv[j] = w;
            }
#pragma unroll
            for (int j = 0; j < 13; j++) {
                int c4 = q + 4 * j;
                __half2 h0 = __floats2half2_rn(vv[j].x, vv[j].y);
                __half2 h1 = __floats2half2_rn(vv[j].z, vv[j].w);
                *(uint2*)(sb + (uint32_t)(e * E_SA2 + c4 * 8)) =
                    make_uint2(*(uint32_t*)&h0, *(uint32_t*)&h1);
            }
            mbar_arrive(bAf + 8 * s);
            s++; if (s == 3) { s = 0; wrap++; }
            it++;
        }
    }
}

// ---------------- node kernel ----------------
#define N_SA2  304
#define N_SLOT 19456u
#define N_HB   58368u
#define N_HSZ  17408u
#define N_SMEM 93184

__global__ __launch_bounds__(512, 1)
void node_tc(const float* __restrict__ x, const float* __restrict__ gf,
             const float* __restrict__ b1, const float* __restrict__ b2,
             float* __restrict__ nout, int N, int ntiles)
{
    __shared__ float b1s[128], b2s[64], redbuf[64];
    __shared__ __align__(16) unsigned long long s_bar[6];
    const int tid = threadIdx.x, lane = tid & 31;
    const uint32_t sbase = smem_u32(dsm);
    const uint32_t bAf = smem_u32(&s_bar[0]), bAe = smem_u32(&s_bar[3]);

    if (tid < 128) b1s[tid] = b1[tid];
    if (tid < 64)  { b2s[tid] = b2[tid]; redbuf[tid] = 0.f; }
    if (tid == 0) {
#pragma unroll
        for (int s = 0; s < 3; s++) {
            mbar_init(bAf + 8 * s, 256);
            mbar_init(bAe + 8 * s, 256);
        }
    }
    __syncthreads();

    if (tid < 256) {  // consumers
        const int wid = tid >> 5, wm = wid >> 2, wn = wid & 3;
        float acc[2][2] = {{0.f, 0.f}, {0.f, 0.f}};
        int s = 0, wrap = 0, it = 0;
        for (int t = blockIdx.x; t < ntiles; t += gridDim.x) {
            mbar_wait(bAf + 8 * s, wrap & 1);
            float d2[2][2][4];
            tile_mlp<N_SA2, 9>(dsm, sbase, s * N_SLOT, N_HB + (uint32_t)(it & 1) * N_HSZ,
                               g_wn1f, g_wn2f, b1s, wm, wn, lane, bAe + 8 * s, d2);
#pragma unroll
            for (int m = 0; m < 2; m++)
#pragma unroll
                for (int h = 0; h < 2; h++) {
                    int row = 32 * wm + 16 * m + (lane >> 2) + 8 * h;
                    int n = t * 64 + row;
                    if (n < N) {
#pragma unroll
                        for (int j = 0; j < 2; j++) {
                            int c = 16 * wn + 8 * j + 2 * (lane & 3);
                            float v0 = d2[m][j][2 * h]     + b2s[c];
                            float v1 = d2[m][j][2 * h + 1] + b2s[c + 1];
                            *(float2*)(nout + (size_t)n * 64 + c) = make_float2(v0, v1);
                            acc[j][0] += v0; acc[j][1] += v1;
                        }
                    }
                }
            s++; if (s == 3) { s = 0; wrap++; }
            it++;
        }
#pragma unroll
        for (int j = 0; j < 2; j++) {
            atomicAdd(&redbuf[16 * wn + 8 * j + 2 * (lane & 3)], acc[j][0]);
            atomicAdd(&redbuf[16 * wn + 8 * j + 2 * (lane & 3) + 1], acc[j][1]);
        }
        BARC256(2);
        if (tid < 64) atomicAdd(&g_nsum[tid], redbuf[tid]);
    } else {  // producers
        const int pt = tid - 256;
        const int e = pt >> 2, q = pt & 3;
        int s = 0, wrap = 0, it = 0;
        for (int t = blockIdx.x; t < ntiles; t += gridDim.x) {
            if (it >= 3) mbar_wait(bAe + 8 * s, (wrap - 1) & 1);
            int n = t * 64 + e;
            bool v = n < N;
            float inv = 1.f;
            if (v) inv = 1.0f / fmaxf(g_cnt[n], 1.0f);
            char* sb = dsm + s * N_SLOT;
            const float4* g4 = (const float4*)gf;
            const float4* xn = (const float4*)(x + (size_t)n * 64);
            const float4* sg = (const float4*)(g_segsum + (size_t)n * 64);
            float4 vv[9];
#pragma unroll
            for (int j = 0; j < 9; j++) {
                int c4 = q + 4 * j;
                float4 w = make_float4(0.f, 0.f, 0.f, 0.f);
                if (v) {
                    if (c4 < 4) w = g4[c4];
                    else if (c4 < 20) w = xn[c4 - 4];
                    else {
                        float4 p = sg[c4 - 20];
                        w = make_float4(p.x * inv, p.y * inv, p.z * inv, p.w * inv);
                    }
                }
                vv[j] = w;
            }
#pragma unroll
            for (int j = 0; j < 9; j++) {
                int c4 = q + 4 * j;
                __half2 h0 = __floats2half2_rn(vv[j].x, vv[j].y);
                __half2 h1 = __floats2half2_rn(vv[j].z, vv[j].w);
                *(uint2*)(sb + (uint32_t)(e * N_SA2 + c4 * 8)) =
                    make_uint2(*(uint32_t*)&h0, *(uint32_t*)&h1);
            }
            mbar_arrive(bAf + 8 * s);
            s++; if (s == 3) { s = 0; wrap++; }
            it++;
        }
    }
}

// ---------------- global kernel ----------------
__global__ void global_kernel(const float* __restrict__ g,
                              const float* __restrict__ Wg1, const float* __restrict__ bg1,
                              const float* __restrict__ Wg2, const float* __restrict__ bg2,
                              float* __restrict__ out, int N, int E)
{
    __shared__ float in[144], h[128];
    int t = threadIdx.x;
    if (t < 64)       in[t] = g_nsum[t] / (float)N;
    else if (t < 128) in[t] = g_esum[t - 64] / (float)E;
    else if (t < 144) in[t] = g[t - 128];
    __syncthreads();
    if (t < 128) {
        float s = bg1[t];
        for (int k = 0; k < 144; k++) s += in[k] * Wg1[(size_t)k * 128 + t];
        h[t] = fmaxf(s, 0.f);
    }
    __syncthreads();
    if (t < 16) {
        float s = bg2[t];
        for (int k = 0; k < 128; k++) s += h[k] * Wg2[(size_t)k * 16 + t];
        out[t] = s;
    }
}

// ---------------- launch ----------------
extern "C" void kernel_launch(void* const* d_in, const int* in_sizes, int n_in,
                              void* d_out, int out_size)
{
    const float* x   = (const float*)d_in[0];
    const int*   ei  = (const int*)d_in[1];
    const float* ea  = (const float*)d_in[2];
    const float* g   = (const float*)d_in[3];
    const float* We1 = (const float*)d_in[4];
    const float* be1 = (const float*)d_in[5];
    const float* We2 = (const float*)d_in[6];
    const float* be2 = (const float*)d_in[7];
    const float* Wn1 = (const float*)d_in[8];
    const float* bn1 = (const float*)d_in[9];
    const float* Wn2 = (const float*)d_in[10];
    const float* bn2 = (const float*)d_in[11];
    const float* Wg1 = (const float*)d_in[12];
    const float* bg1 = (const float*)d_in[13];
    const float* Wg2 = (const float*)d_in[14];
    const float* bg2 = (const float*)d_in[15];

    int N = in_sizes[0] / 64;
    int E = in_sizes[1] / 2;
    float* eout = (float*)d_out;
    float* nout = eout + (size_t)E * 64;
    float* gout = nout + (size_t)N * 64;

    cudaFuncSetAttribute(edge_tc, cudaFuncAttributeMaxDynamicSharedMemorySize, E_SMEM);
    cudaFuncSetAttribute(node_tc, cudaFuncAttributeMaxDynamicSharedMemorySize, N_SMEM);

    setup_kernel<<<(N * 16 + 255) / 256, 256>>>(N, We1, We2, Wn1, Wn2);

    int etiles = (E + 63) / 64;
    int ntl    = (N + 63) / 64;
    edge_tc<<<148, 512, E_SMEM>>>(x, ei, ea, g, be1, be2, eout, E, N, etiles);
    node_tc<<<148, 512, N_SMEM>>>(x, g, bn1, bn2, nout, N, ntl);
    global_kernel<<<1, 160>>>(g, Wg1, bg1, Wg2, bg2, gout, N, E);
}